// round 4
// baseline (speedup 1.0000x reference)
#include <cuda_runtime.h>
#include <math.h>

constexpr int B_  = 8;
constexpr int N_  = 512;
constexpr int M_  = 512;
constexpr int D_  = 512;
constexpr int ND_ = N_ + M_ - 1;   // 1023 anti-diagonals
constexpr float NEGL    = -1.0e9f;
constexpr float INV_LN2 = 1.44269504088896340736f;

// Diagonal-major scratch (zero-initialized; invalid slots are never written,
// so they stay zero — bwd relies on this for implicit masking).
__device__ float2 g_tha[(size_t)B_ * ND_ * N_];
__device__ float2 g_w  [(size_t)B_ * ND_ * N_];
__device__ float  g_e  [(size_t)B_ * ND_ * N_];

__device__ __forceinline__ float ex2f_(float x) { float y; asm("ex2.approx.ftz.f32 %0, %1;" : "=f"(y) : "f"(x)); return y; }
__device__ __forceinline__ float lg2f_(float x) { float y; asm("lg2.approx.f32 %0, %1;"     : "=f"(y) : "f"(x)); return y; }
__device__ __forceinline__ float rcpf_(float x) { float y; asm("rcp.approx.f32 %0, %1;"     : "=f"(y) : "f"(x)); return y; }

// -------- smem relaxed/acquire-release helpers (cross-warp handoff) --------
__device__ __forceinline__ unsigned smaddr_(const void* p) {
    return (unsigned)__cvta_generic_to_shared(p);
}
__device__ __forceinline__ unsigned long long lds_relax64(const unsigned long long* p) {
    unsigned long long v;
    asm volatile("ld.relaxed.cta.shared.b64 %0, [%1];" : "=l"(v) : "r"(smaddr_(p)));
    return v;
}
__device__ __forceinline__ void sts_relax64(unsigned long long* p, unsigned long long v) {
    asm volatile("st.relaxed.cta.shared.b64 [%0], %1;" :: "r"(smaddr_(p)), "l"(v));
}
__device__ __forceinline__ unsigned long long lds_acq64(const unsigned long long* p) {
    unsigned long long v;
    asm volatile("ld.acquire.cta.shared.b64 %0, [%1];" : "=l"(v) : "r"(smaddr_(p)));
    return v;
}
__device__ __forceinline__ void sts_rel64(unsigned long long* p, unsigned long long v) {
    asm volatile("st.release.cta.shared.b64 [%0], %1;" :: "r"(smaddr_(p)), "l"(v));
}
__device__ __forceinline__ int lds_relax32(const int* p) {
    int v; asm volatile("ld.relaxed.cta.shared.b32 %0, [%1];" : "=r"(v) : "r"(smaddr_(p))); return v;
}
__device__ __forceinline__ void sts_relax32(int* p, int v) {
    asm volatile("st.relaxed.cta.shared.b32 [%0], %1;" :: "r"(smaddr_(p)), "r"(v));
}
__device__ __forceinline__ unsigned long long packtv_(int tag, float v) {
    return ((unsigned long long)__float_as_uint(v) << 32) | (unsigned)tag;
}

// ---------------------------------------------------------------------------
// GEMM + activation (unchanged): 128x128 tile, 256 thr, 8x8 micro.
// ---------------------------------------------------------------------------
__global__ void __launch_bounds__(256, 2) gemm_act_kernel(
    const float* __restrict__ zx, const float* __restrict__ zy,
    const float* __restrict__ gx, const float* __restrict__ gy,
    float* __restrict__ out)
{
    const int mz  = blockIdx.z;
    const int b   = mz & 7;
    const int sel = mz >> 3;
    const float* X = (sel ? gx : zx) + (size_t)b * N_ * D_;
    const float* Y = (sel ? gy : zy) + (size_t)b * M_ * D_;
    float* C = out + (size_t)(1 + sel) * B_ * N_ * M_ + (size_t)b * N_ * M_;

    const int row0 = blockIdx.y * 128;
    const int col0 = blockIdx.x * 128;

    __shared__ float Xs[16][132];
    __shared__ float Ys[16][132];

    const int t  = threadIdx.x;
    const int lr = t >> 1;
    const int lk = (t & 1) * 8;
    const int ty = t >> 4;
    const int tx = t & 15;

    float acc[8][8];
#pragma unroll
    for (int r = 0; r < 8; ++r)
#pragma unroll
        for (int c = 0; c < 8; ++c) acc[r][c] = 0.f;

    for (int k0 = 0; k0 < D_; k0 += 16) {
        const float4 xv0 = *(const float4*)(X + (size_t)(row0 + lr) * D_ + k0 + lk);
        const float4 xv1 = *(const float4*)(X + (size_t)(row0 + lr) * D_ + k0 + lk + 4);
        const float4 yv0 = *(const float4*)(Y + (size_t)(col0 + lr) * D_ + k0 + lk);
        const float4 yv1 = *(const float4*)(Y + (size_t)(col0 + lr) * D_ + k0 + lk + 4);
        __syncthreads();
        Xs[lk + 0][lr] = xv0.x; Xs[lk + 1][lr] = xv0.y; Xs[lk + 2][lr] = xv0.z; Xs[lk + 3][lr] = xv0.w;
        Xs[lk + 4][lr] = xv1.x; Xs[lk + 5][lr] = xv1.y; Xs[lk + 6][lr] = xv1.z; Xs[lk + 7][lr] = xv1.w;
        Ys[lk + 0][lr] = yv0.x; Ys[lk + 1][lr] = yv0.y; Ys[lk + 2][lr] = yv0.z; Ys[lk + 3][lr] = yv0.w;
        Ys[lk + 4][lr] = yv1.x; Ys[lk + 5][lr] = yv1.y; Ys[lk + 6][lr] = yv1.z; Ys[lk + 7][lr] = yv1.w;
        __syncthreads();
#pragma unroll
        for (int kk = 0; kk < 16; ++kk) {
            float a0[8], b0[8];
            *(float4*)(a0)     = *(const float4*)&Xs[kk][ty * 8];
            *(float4*)(a0 + 4) = *(const float4*)&Xs[kk][ty * 8 + 4];
            *(float4*)(b0)     = *(const float4*)&Ys[kk][tx * 8];
            *(float4*)(b0 + 4) = *(const float4*)&Ys[kk][tx * 8 + 4];
#pragma unroll
            for (int r = 0; r < 8; ++r)
#pragma unroll
                for (int c = 0; c < 8; ++c)
                    acc[r][c] = fmaf(a0[r], b0[c], acc[r][c]);
        }
    }

#pragma unroll
    for (int r = 0; r < 8; ++r) {
        const int row = row0 + ty * 8 + r;
#pragma unroll
        for (int c4 = 0; c4 < 8; c4 += 4) {
            float4 v;
            float* vp = &v.x;
#pragma unroll
            for (int q = 0; q < 4; ++q) {
                const float x = acc[r][c4 + q];
                const float l = log1pf(__expf(-fabsf(x)));
                vp[q] = sel ? (fminf(x, 0.f) - l)     // log_sigmoid
                            : (fmaxf(x, 0.f) + l);    // softplus
            }
            *(float4*)(C + (size_t)row * M_ + col0 + tx * 8 + c4) = v;
        }
    }
}

// ---------------------------------------------------------------------------
// Diagonalize: theta,A (row-major) -> g_tha (diag-major float2, pre-scaled).
// ---------------------------------------------------------------------------
__global__ void __launch_bounds__(256) diag_kernel(const float* __restrict__ out)
{
    const float* theta = out + (size_t)B_ * N_ * M_;
    const float* Ag    = out + (size_t)2 * B_ * N_ * M_;
    const int b  = blockIdx.z;
    const int i0 = blockIdx.y * 32;
    const int j0 = blockIdx.x * 32;

    __shared__ float sth[32 * 32];
    __shared__ float sa [32 * 32];

    const int t    = threadIdx.x;
    const int warp = t >> 5;
    const int lane = t & 31;

#pragma unroll
    for (int it = 0; it < 4; ++it) {
        const int r = warp + it * 8;
        const int c = lane;
        const size_t g = ((size_t)b * N_ + (i0 + r)) * M_ + (j0 + c);
        sth[r * 32 + c] = theta[g] * INV_LN2;
        sa [r * 32 + c] = Ag[g]    * INV_LN2;
    }
    __syncthreads();

    float2* dst = g_tha + (size_t)b * ND_ * N_;
#pragma unroll
    for (int dd0 = 0; dd0 < 64; dd0 += 8) {
        const int dd = dd0 + warp;
        const int il = lane;
        const int jl = dd - il;
        if ((unsigned)jl < 32u) {
            const int d = i0 + j0 + dd;
            dst[(size_t)d * N_ + (i0 + il)] = make_float2(sth[il * 32 + jl], sa[il * 32 + jl]);
        }
    }
}

// ---------------------------------------------------------------------------
// Undiagonalize: g_e (diag-major) -> aln (row-major).
// ---------------------------------------------------------------------------
__global__ void __launch_bounds__(256) undiag_kernel(float* __restrict__ out)
{
    const int b  = blockIdx.z;
    const int i0 = blockIdx.y * 32;
    const int j0 = blockIdx.x * 32;

    __shared__ float se[32 * 32];

    const int t    = threadIdx.x;
    const int warp = t >> 5;
    const int lane = t & 31;

    const float* src = g_e + (size_t)b * ND_ * N_;
#pragma unroll
    for (int dd0 = 0; dd0 < 64; dd0 += 8) {
        const int dd = dd0 + warp;
        const int il = lane;
        const int jl = dd - il;
        if ((unsigned)jl < 32u) {
            const int d = i0 + j0 + dd;
            se[il * 32 + jl] = src[(size_t)d * N_ + (i0 + il)];
        }
    }
    __syncthreads();

    float* alnB = out + (size_t)b * N_ * M_;
#pragma unroll
    for (int it = 0; it < 4; ++it) {
        const int r = warp + it * 8;
        const int c = lane;
        alnB[(size_t)(i0 + r) * M_ + (j0 + c)] = se[r * 32 + c];
    }
}

// ---------------------------------------------------------------------------
// Forward soft-NW: warp-skew systolic pipeline. Lane owns row r = tid.
// Neighbor V values via shfl_up; warp boundaries via tagged smem ring
// (relaxed b64 packets). No __syncthreads in the main loop.
// ---------------------------------------------------------------------------
__global__ void __launch_bounds__(512) nw_fwd_kernel()
{
    const int b    = blockIdx.x;
    const int tid  = threadIdx.x;
    const int wid  = tid >> 5;
    const int lane = tid & 31;
    const int r    = tid;          // row index, i = r + 1
    const int w0   = wid * 32;

    __shared__ unsigned long long ringV[15][128];
    __shared__ int prog[16];

    for (int idx = tid; idx < 15 * 128; idx += 512)
        ((unsigned long long*)ringV)[idx] = 0xFFFFFFFFFFFFFFFFULL;
    if (tid < 16) prog[tid] = tid * 32 - 2;
    __syncthreads();   // once, before the pipeline starts

    const float2* THA = g_tha + (size_t)b * ND_ * N_;
    float2*       Wb  = g_w   + (size_t)b * ND_ * N_;

    const int dHi = w0 + 542;      // warp covers d in [w0, w0+542]

    // depth-6 register prefetch queue for (theta, A) along own row
    float2 t0 = THA[(size_t)(w0 + 0) * N_ + r];
    float2 t1 = THA[(size_t)(w0 + 1) * N_ + r];
    float2 t2 = THA[(size_t)(w0 + 2) * N_ + r];
    float2 t3 = THA[(size_t)(w0 + 3) * N_ + r];
    float2 t4 = THA[(size_t)(w0 + 4) * N_ + r];
    float2 t5 = THA[(size_t)(w0 + 5) * N_ + r];

    float vp     = NEGL;                                   // my V at d-1
    float nbPrev = (tid == 0) ? 0.f : NEGL;                // neighbor V at d-2 (V[0,0]=0 seed)

    for (int d = w0; d <= dHi; ++d) {
        // prefetch theta/A for d+6
        float2 tn = make_float2(0.f, 0.f);
        const int dp = d + 6;
        if (dp <= dHi) tn = THA[(size_t)dp * N_ + r];

        // neighbor V at d-1
        float nb = __shfl_up_sync(0xffffffffu, vp, 1);
        const bool active = (unsigned)(d - r) < (unsigned)M_;
        if (lane == 0) {
            nb = NEGL;
            if (wid > 0 && active) {
                const int t = d - 1;
                unsigned long long p;
                do { p = lds_relax64(&ringV[wid - 1][t & 127]); } while ((unsigned)p != (unsigned)t);
                nb = __uint_as_float((unsigned)(p >> 32));
            }
        }

        const float x0 = t0.y + nb;        // A + V[i-1, j]
        const float x2 = t0.y + vp;        // A + V[i,   j-1]
        const float dg = nbPrev;           //     V[i-1, j-1]
        const float m  = fmaxf(fmaxf(x0, x2), dg);
        const float e0 = ex2f_(x0 - m);
        const float e1 = ex2f_(dg - m);
        const float e2 = ex2f_(x2 - m);
        const float s  = e0 + e1 + e2;
        const float rr = rcpf_(s);
        const float v  = t0.x + m + lg2f_(s);

        if (active) {
            Wb[(size_t)d * N_ + r] = make_float2(e0 * rr, e2 * rr);
            vp = v;
        }
        nbPrev = nb;

        if (lane == 31 && wid < 15 && active)
            sts_relax64(&ringV[wid][d & 127], packtv_(d, v));

        if ((d & 31) == 31) {
            if (lane == 0 && wid > 0) sts_relax32(&prog[wid], d);
            if (lane == 31 && wid < 15)
                while ((d + 32) - lds_relax32(&prog[wid + 1]) > 96) { }
        }

        t0 = t1; t1 = t2; t2 = t3; t3 = t4; t4 = t5; t5 = tn;
    }
    if (lane == 0 && wid > 0) sts_relax32(&prog[wid], 0x3f000000);
}

// ---------------------------------------------------------------------------
// Backward soft-NW: mirrored warp-skew pipeline (dependency flows from high
// rows to low rows). E and W neighbor values via shfl_down; warp boundary
// packets = (tag,E) release-store + (wU,wL) plain store; consumer acquires.
// Own-row W stream with depth-6 register prefetch (one LDG.64/lane/step).
// ---------------------------------------------------------------------------
__global__ void __launch_bounds__(512) nw_bwd_kernel()
{
    const int b    = blockIdx.x;
    const int tid  = threadIdx.x;
    const int wid  = tid >> 5;
    const int lane = tid & 31;
    const int r    = tid;
    const int w0   = wid * 32;

    __shared__ unsigned long long ringE[15][128];
    __shared__ unsigned long long ringW[15][128];
    __shared__ int prog[16];

    for (int idx = tid; idx < 15 * 128; idx += 512) {
        ((unsigned long long*)ringE)[idx] = 0xFFFFFFFFFFFFFFFFULL;
        ((unsigned long long*)ringW)[idx] = 0ULL;
    }
    if (tid < 16) prog[tid] = tid * 32 + 544;
    __syncthreads();

    const float2* Wb = g_w + (size_t)b * ND_ * N_;
    float*        Eb = g_e + (size_t)b * ND_ * N_;

    const int dHi = w0 + 542;

    // depth-6 register prefetch queue for own-row weights W[d][r]
    float2 q0 = Wb[(size_t)(dHi - 0) * N_ + r];
    float2 q1 = Wb[(size_t)(dHi - 1) * N_ + r];
    float2 q2 = Wb[(size_t)(dHi - 2) * N_ + r];
    float2 q3 = Wb[(size_t)(dHi - 3) * N_ + r];
    float2 q4 = Wb[(size_t)(dHi - 4) * N_ + r];
    float2 q5 = Wb[(size_t)(dHi - 5) * N_ + r];

    float2 wp      = make_float2(0.f, 0.f);   // W[d+1][r]
    float  ep      = 0.f;                     // my E at d+1
    float  nbEPrev = 0.f;                     // neighbor E at d+2
    float2 nbWPrev = make_float2(0.f, 0.f);   // neighbor W at d+2

    for (int d = dHi; d >= w0; --d) {
        // prefetch W for d-6
        float2 wn = make_float2(0.f, 0.f);
        const int dp = d - 6;
        if (dp >= 0) wn = Wb[(size_t)dp * N_ + r];

        // neighbor (row r+1) E and W at d+1
        float nbE  = __shfl_down_sync(0xffffffffu, ep, 1);
        float nbWx = __shfl_down_sync(0xffffffffu, wp.x, 1);
        float nbWy = __shfl_down_sync(0xffffffffu, wp.y, 1);
        const bool active = (unsigned)(d - r) < (unsigned)M_;
        if (lane == 31) {
            nbE = 0.f; nbWx = 0.f; nbWy = 0.f;
            if (wid < 15 && active) {
                const int t = d + 1;
                unsigned long long p;
                do { p = lds_acq64(&ringE[wid][t & 127]); } while ((unsigned)p != (unsigned)t);
                nbE = __uint_as_float((unsigned)(p >> 32));
                const unsigned long long w2 = ((const unsigned long long*)ringW[wid])[t & 127];
                nbWx = __uint_as_float((unsigned)(w2 & 0xFFFFFFFFu));
                nbWy = __uint_as_float((unsigned)(w2 >> 32));
            }
        }

        float e = nbE * nbWx
                + ep  * wp.y
                + nbEPrev * (1.f - nbWPrev.x - nbWPrev.y);
        if (d == 1022 && r == 511) e = 1.f;   // base case E[N, M] = 1

        if (active) {
            Eb[(size_t)d * N_ + r] = e;
            ep = e;
        }
        nbEPrev = nbE;
        nbWPrev = make_float2(nbWx, nbWy);

        if (lane == 0 && wid > 0 && active) {
            const unsigned long long w2 =
                ((unsigned long long)__float_as_uint(q0.y) << 32) | __float_as_uint(q0.x);
            sts_relax64(&ringW[wid - 1][d & 127], w2);
            sts_rel64 (&ringE[wid - 1][d & 127], packtv_(d, e));
        }

        if ((d & 31) == 0) {
            if (lane == 31 && wid < 15) sts_relax32(&prog[wid], d);
            if (lane == 0 && wid > 0)
                while (lds_relax32(&prog[wid - 1]) - (d - 32) > 96) { }
        }

        wp = q0; q0 = q1; q1 = q2; q2 = q3; q3 = q4; q4 = q5; q5 = wn;
    }
    if (lane == 31 && wid < 15) sts_relax32(&prog[wid], -0x3f000000);
}

// ---------------------------------------------------------------------------
// launch
// ---------------------------------------------------------------------------
extern "C" void kernel_launch(void* const* d_in, const int* in_sizes, int n_in,
                              void* d_out, int out_size)
{
    const float* zx = (const float*)d_in[0];
    const float* zy = (const float*)d_in[1];
    const float* gx = (const float*)d_in[2];
    const float* gy = (const float*)d_in[3];
    float* out = (float*)d_out;   // [aln | theta | A]

    dim3 ggrid(M_ / 128, N_ / 128, 2 * B_);
    gemm_act_kernel<<<ggrid, 256>>>(zx, zy, gx, gy, out);

    dim3 tgrid(M_ / 32, N_ / 32, B_);
    diag_kernel<<<tgrid, 256>>>(out);
    nw_fwd_kernel<<<B_, 512>>>();
    nw_bwd_kernel<<<B_, 512>>>();
    undiag_kernel<<<tgrid, 256>>>(out);
}

// round 5
// speedup vs baseline: 2.2655x; 2.2655x over previous
#include <cuda_runtime.h>
#include <math.h>

constexpr int B_  = 8;
constexpr int N_  = 512;
constexpr int M_  = 512;
constexpr int D_  = 512;
constexpr int ND_ = N_ + M_ - 1;   // 1023 anti-diagonals
constexpr float NEGL    = -1.0e9f;
constexpr float INV_LN2 = 1.44269504088896340736f;

// Diagonal-major scratch (zero-initialized; invalid slots are never written,
// so they stay zero — bwd relies on this for implicit masking).
__device__ float2 g_tha[(size_t)B_ * ND_ * N_];
__device__ float2 g_w  [(size_t)B_ * ND_ * N_];
__device__ float  g_e  [(size_t)B_ * ND_ * N_];

__device__ __forceinline__ float ex2f_(float x) { float y; asm("ex2.approx.ftz.f32 %0, %1;" : "=f"(y) : "f"(x)); return y; }
__device__ __forceinline__ float lg2f_(float x) { float y; asm("lg2.approx.f32 %0, %1;"     : "=f"(y) : "f"(x)); return y; }
__device__ __forceinline__ float rcpf_(float x) { float y; asm("rcp.approx.f32 %0, %1;"     : "=f"(y) : "f"(x)); return y; }

// ---------------------------------------------------------------------------
// GEMM + activation (unchanged): 128x128 tile, 256 thr, 8x8 micro.
// ---------------------------------------------------------------------------
__global__ void __launch_bounds__(256, 2) gemm_act_kernel(
    const float* __restrict__ zx, const float* __restrict__ zy,
    const float* __restrict__ gx, const float* __restrict__ gy,
    float* __restrict__ out)
{
    const int mz  = blockIdx.z;
    const int b   = mz & 7;
    const int sel = mz >> 3;
    const float* X = (sel ? gx : zx) + (size_t)b * N_ * D_;
    const float* Y = (sel ? gy : zy) + (size_t)b * M_ * D_;
    float* C = out + (size_t)(1 + sel) * B_ * N_ * M_ + (size_t)b * N_ * M_;

    const int row0 = blockIdx.y * 128;
    const int col0 = blockIdx.x * 128;

    __shared__ float Xs[16][132];
    __shared__ float Ys[16][132];

    const int t  = threadIdx.x;
    const int lr = t >> 1;
    const int lk = (t & 1) * 8;
    const int ty = t >> 4;
    const int tx = t & 15;

    float acc[8][8];
#pragma unroll
    for (int r = 0; r < 8; ++r)
#pragma unroll
        for (int c = 0; c < 8; ++c) acc[r][c] = 0.f;

    for (int k0 = 0; k0 < D_; k0 += 16) {
        const float4 xv0 = *(const float4*)(X + (size_t)(row0 + lr) * D_ + k0 + lk);
        const float4 xv1 = *(const float4*)(X + (size_t)(row0 + lr) * D_ + k0 + lk + 4);
        const float4 yv0 = *(const float4*)(Y + (size_t)(col0 + lr) * D_ + k0 + lk);
        const float4 yv1 = *(const float4*)(Y + (size_t)(col0 + lr) * D_ + k0 + lk + 4);
        __syncthreads();
        Xs[lk + 0][lr] = xv0.x; Xs[lk + 1][lr] = xv0.y; Xs[lk + 2][lr] = xv0.z; Xs[lk + 3][lr] = xv0.w;
        Xs[lk + 4][lr] = xv1.x; Xs[lk + 5][lr] = xv1.y; Xs[lk + 6][lr] = xv1.z; Xs[lk + 7][lr] = xv1.w;
        Ys[lk + 0][lr] = yv0.x; Ys[lk + 1][lr] = yv0.y; Ys[lk + 2][lr] = yv0.z; Ys[lk + 3][lr] = yv0.w;
        Ys[lk + 4][lr] = yv1.x; Ys[lk + 5][lr] = yv1.y; Ys[lk + 6][lr] = yv1.z; Ys[lk + 7][lr] = yv1.w;
        __syncthreads();
#pragma unroll
        for (int kk = 0; kk < 16; ++kk) {
            float a0[8], b0[8];
            *(float4*)(a0)     = *(const float4*)&Xs[kk][ty * 8];
            *(float4*)(a0 + 4) = *(const float4*)&Xs[kk][ty * 8 + 4];
            *(float4*)(b0)     = *(const float4*)&Ys[kk][tx * 8];
            *(float4*)(b0 + 4) = *(const float4*)&Ys[kk][tx * 8 + 4];
#pragma unroll
            for (int r = 0; r < 8; ++r)
#pragma unroll
                for (int c = 0; c < 8; ++c)
                    acc[r][c] = fmaf(a0[r], b0[c], acc[r][c]);
        }
    }

#pragma unroll
    for (int r = 0; r < 8; ++r) {
        const int row = row0 + ty * 8 + r;
#pragma unroll
        for (int c4 = 0; c4 < 8; c4 += 4) {
            float4 v;
            float* vp = &v.x;
#pragma unroll
            for (int q = 0; q < 4; ++q) {
                const float x = acc[r][c4 + q];
                const float l = log1pf(__expf(-fabsf(x)));
                vp[q] = sel ? (fminf(x, 0.f) - l)     // log_sigmoid
                            : (fmaxf(x, 0.f) + l);    // softplus
            }
            *(float4*)(C + (size_t)row * M_ + col0 + tx * 8 + c4) = v;
        }
    }
}

// ---------------------------------------------------------------------------
// Diagonalize: theta,A (row-major) -> g_tha (diag-major float2, pre-scaled).
// ---------------------------------------------------------------------------
__global__ void __launch_bounds__(256) diag_kernel(const float* __restrict__ out)
{
    const float* theta = out + (size_t)B_ * N_ * M_;
    const float* Ag    = out + (size_t)2 * B_ * N_ * M_;
    const int b  = blockIdx.z;
    const int i0 = blockIdx.y * 32;
    const int j0 = blockIdx.x * 32;

    __shared__ float sth[32 * 32];
    __shared__ float sa [32 * 32];

    const int t    = threadIdx.x;
    const int warp = t >> 5;
    const int lane = t & 31;

#pragma unroll
    for (int it = 0; it < 4; ++it) {
        const int r = warp + it * 8;
        const int c = lane;
        const size_t g = ((size_t)b * N_ + (i0 + r)) * M_ + (j0 + c);
        sth[r * 32 + c] = theta[g] * INV_LN2;
        sa [r * 32 + c] = Ag[g]    * INV_LN2;
    }
    __syncthreads();

    float2* dst = g_tha + (size_t)b * ND_ * N_;
#pragma unroll
    for (int dd0 = 0; dd0 < 64; dd0 += 8) {
        const int dd = dd0 + warp;
        const int il = lane;
        const int jl = dd - il;
        if ((unsigned)jl < 32u) {
            const int d = i0 + j0 + dd;
            dst[(size_t)d * N_ + (i0 + il)] = make_float2(sth[il * 32 + jl], sa[il * 32 + jl]);
        }
    }
}

// ---------------------------------------------------------------------------
// Undiagonalize: g_e (diag-major) -> aln (row-major).
// ---------------------------------------------------------------------------
__global__ void __launch_bounds__(256) undiag_kernel(float* __restrict__ out)
{
    const int b  = blockIdx.z;
    const int i0 = blockIdx.y * 32;
    const int j0 = blockIdx.x * 32;

    __shared__ float se[32 * 32];

    const int t    = threadIdx.x;
    const int warp = t >> 5;
    const int lane = t & 31;

    const float* src = g_e + (size_t)b * ND_ * N_;
#pragma unroll
    for (int dd0 = 0; dd0 < 64; dd0 += 8) {
        const int dd = dd0 + warp;
        const int il = lane;
        const int jl = dd - il;
        if ((unsigned)jl < 32u) {
            const int d = i0 + j0 + dd;
            se[il * 32 + jl] = src[(size_t)d * N_ + (i0 + il)];
        }
    }
    __syncthreads();

    float* alnB = out + (size_t)b * N_ * M_;
#pragma unroll
    for (int it = 0; it < 4; ++it) {
        const int r = warp + it * 8;
        const int c = lane;
        alnB[(size_t)(i0 + r) * M_ + (j0 + c)] = se[r * 32 + c];
    }
}

// ---------------------------------------------------------------------------
// Forward soft-NW: wavefront of 32x32 tiles. Warp w owns rows [32w, 32w+32);
// within a tile, 32 diagonal steps run in registers with shfl_up for the
// neighbor row. Warp-boundary row values go through a plain smem ring; the
// tile schedule (wave t: warp w runs chunk c = t - 2w) guarantees every ring
// read is >= 1 __syncthreads after its write. 47 barriers total.
// ---------------------------------------------------------------------------
__global__ void __launch_bounds__(512) nw_fwd_kernel()
{
    const int b    = blockIdx.x;
    const int tid  = threadIdx.x;
    const int wid  = tid >> 5;
    const int lane = tid & 31;
    const int r    = tid;          // row index, i = r + 1
    const int w0   = wid * 32;

    __shared__ float bndV[16][128];   // [wid][d & 127] — lane31 V of warp wid
    for (int i = tid; i < 16 * 128; i += 512) ((float*)bndV)[i] = NEGL;
    __syncthreads();

    const float2* THA = g_tha + (size_t)b * ND_ * N_;
    float2*       Wb  = g_w   + (size_t)b * ND_ * N_;

    // 8-deep rolling register queue for (theta, A) along own row
    float2 th[8];
#pragma unroll
    for (int q = 0; q < 8; ++q) th[q] = THA[(size_t)(w0 + q) * N_ + r];

    float vp     = NEGL;                     // my V at previous diagonal
    float nbPrev = (tid == 0) ? 0.f : NEGL;  // neighbor V two diagonals back (V[0,0]=0 seed)

    for (int t = 0; t < 47; ++t) {
        const int c = t - 2 * wid;
        if (c >= 0 && c < 17) {
            const int d0 = w0 + 32 * c;
#pragma unroll
            for (int s = 0; s < 32; ++s) {
                const int d = d0 + s;
                const float2 ta = th[s & 7];
                {   // prefetch d+8 (clamped; out-of-band values are never used)
                    int dp = d + 8; if (dp > ND_ - 1) dp = ND_ - 1;
                    th[s & 7] = THA[(size_t)dp * N_ + r];
                }
                float nb = __shfl_up_sync(0xffffffffu, vp, 1);
                if (lane == 0) nb = (wid > 0) ? bndV[wid - 1][(d - 1) & 127] : NEGL;

                const float x0 = ta.y + nb;        // A + V[i-1, j]
                const float x2 = ta.y + vp;        // A + V[i,   j-1]
                const float dg = nbPrev;           //     V[i-1, j-1]
                const float m  = fmaxf(fmaxf(x0, x2), dg);
                const float e0 = ex2f_(x0 - m);
                const float e1 = ex2f_(dg - m);
                const float e2 = ex2f_(x2 - m);
                const float ss = e0 + e1 + e2;
                const float rr = rcpf_(ss);
                const float v  = ta.x + m + lg2f_(ss);

                const bool active = (unsigned)(d - r) < (unsigned)M_;
                if (active) {
                    Wb[(size_t)d * N_ + r] = make_float2(e0 * rr, e2 * rr);
                    vp = v;
                    if (lane == 31 && wid < 15) bndV[wid][d & 127] = v;
                }
                nbPrev = nb;
            }
        }
        __syncthreads();
    }
}

// ---------------------------------------------------------------------------
// Backward soft-NW: mirrored tile wavefront (dependency flows high->low rows).
// E[i,j] = E[i+1,j]*wU(i+1,j) + E[i,j+1]*wL(i,j+1) + E[i+1,j+1]*wD(i+1,j+1),
// E[N,M] = 1, wD = 1 - wU - wL. Zero weights/E outside the valid region make
// all masking implicit. Wave t: warp w runs chunk cc = t - 2*(15 - w).
// ---------------------------------------------------------------------------
__global__ void __launch_bounds__(512) nw_bwd_kernel()
{
    const int b    = blockIdx.x;
    const int tid  = threadIdx.x;
    const int wid  = tid >> 5;
    const int lane = tid & 31;
    const int r    = tid;
    const int w0   = wid * 32;
    const int dTop = w0 + 542;

    __shared__ float  eRing[15][128];   // [wid][d & 127] — lane0 E of warp wid+1
    __shared__ float2 wRing[15][128];   // matching own-row W of that lane
    for (int i = tid; i < 15 * 128; i += 512) {
        ((float*)eRing)[i]  = 0.f;
        ((float2*)wRing)[i] = make_float2(0.f, 0.f);
    }
    __syncthreads();

    const float2* Wb = g_w + (size_t)b * ND_ * N_;
    float*        Eb = g_e + (size_t)b * ND_ * N_;

    // 8-deep rolling register queue for own-row weights W[d][r] (descending d)
    float2 wq8[8];
#pragma unroll
    for (int q = 0; q < 8; ++q) wq8[q] = Wb[(size_t)(dTop - q) * N_ + r];

    float2 wp      = make_float2(0.f, 0.f);  // W[d+1][r]
    float  ep      = 0.f;                    // my E at d+1
    float  nbEPrev = 0.f;                    // neighbor (row r+1) E at d+2
    float2 nbWPrev = make_float2(0.f, 0.f);  // neighbor W at d+2

    for (int t = 0; t < 47; ++t) {
        const int cc = t - 2 * (15 - wid);
        if (cc >= 0 && cc < 17) {
#pragma unroll
            for (int s = 0; s < 32; ++s) {
                const int d = dTop - 32 * cc - s;
                const float2 wq = wq8[s & 7];     // W[d][r]
                {   // prefetch d-8 (clamped; out-of-band values never used)
                    int dp = d - 8; if (dp < 0) dp = 0;
                    wq8[s & 7] = Wb[(size_t)dp * N_ + r];
                }
                float nbE  = __shfl_down_sync(0xffffffffu, ep, 1);
                float nbWx = __shfl_down_sync(0xffffffffu, wp.x, 1);
                float nbWy = __shfl_down_sync(0xffffffffu, wp.y, 1);
                if (lane == 31) {
                    if (wid < 15) {
                        nbE = eRing[wid][(d + 1) & 127];
                        const float2 wv = wRing[wid][(d + 1) & 127];
                        nbWx = wv.x; nbWy = wv.y;
                    } else {
                        nbE = 0.f; nbWx = 0.f; nbWy = 0.f;
                    }
                }

                float e = nbE * nbWx                                  // E[i+1,j]   * wU(i+1,j)
                        + ep  * wp.y                                  // E[i,j+1]   * wL(i,j+1)
                        + nbEPrev * (1.f - nbWPrev.x - nbWPrev.y);    // E[i+1,j+1] * wD(i+1,j+1)
                if (r == 511 && d == 1022) e = 1.f;                   // base case E[N,M]

                const bool active = (unsigned)(d - r) < (unsigned)M_;
                if (active) {
                    Eb[(size_t)d * N_ + r] = e;
                    ep = e;
                    if (lane == 0 && wid > 0) {
                        wRing[wid - 1][d & 127] = wq;
                        eRing[wid - 1][d & 127] = e;
                    }
                }
                nbEPrev = nbE;
                nbWPrev = make_float2(nbWx, nbWy);
                wp = wq;
            }
        }
        __syncthreads();
    }
}

// ---------------------------------------------------------------------------
// launch
// ---------------------------------------------------------------------------
extern "C" void kernel_launch(void* const* d_in, const int* in_sizes, int n_in,
                              void* d_out, int out_size)
{
    const float* zx = (const float*)d_in[0];
    const float* zy = (const float*)d_in[1];
    const float* gx = (const float*)d_in[2];
    const float* gy = (const float*)d_in[3];
    float* out = (float*)d_out;   // [aln | theta | A]

    dim3 ggrid(M_ / 128, N_ / 128, 2 * B_);
    gemm_act_kernel<<<ggrid, 256>>>(zx, zy, gx, gy, out);

    dim3 tgrid(M_ / 32, N_ / 32, B_);
    diag_kernel<<<tgrid, 256>>>(out);
    nw_fwd_kernel<<<B_, 512>>>();
    nw_bwd_kernel<<<B_, 512>>>();
    undiag_kernel<<<tgrid, 256>>>(out);
}

// round 6
// speedup vs baseline: 2.2796x; 1.0062x over previous
#include <cuda_runtime.h>
#include <math.h>

constexpr int B_  = 8;
constexpr int N_  = 512;
constexpr int M_  = 512;
constexpr int D_  = 512;
constexpr int ND_ = N_ + M_ - 1;   // 1023 anti-diagonals
constexpr float NEGL    = -1.0e9f;
constexpr float INV_LN2 = 1.44269504088896340736f;

// Diagonal-major scratch (zero-initialized; invalid slots are never written,
// so they stay zero — bwd relies on this for implicit masking).
__device__ float2 g_tha[(size_t)B_ * ND_ * N_];
__device__ float2 g_w  [(size_t)B_ * ND_ * N_];
__device__ float  g_e  [(size_t)B_ * ND_ * N_];

__device__ __forceinline__ float ex2f_(float x) { float y; asm("ex2.approx.ftz.f32 %0, %1;" : "=f"(y) : "f"(x)); return y; }
__device__ __forceinline__ float lg2f_(float x) { float y; asm("lg2.approx.f32 %0, %1;"     : "=f"(y) : "f"(x)); return y; }
__device__ __forceinline__ float rcpf_(float x) { float y; asm("rcp.approx.f32 %0, %1;"     : "=f"(y) : "f"(x)); return y; }

// ---------------------------------------------------------------------------
// GEMM + activation (unchanged): 128x128 tile, 256 thr, 8x8 micro.
// ---------------------------------------------------------------------------
__global__ void __launch_bounds__(256, 2) gemm_act_kernel(
    const float* __restrict__ zx, const float* __restrict__ zy,
    const float* __restrict__ gx, const float* __restrict__ gy,
    float* __restrict__ out)
{
    const int mz  = blockIdx.z;
    const int b   = mz & 7;
    const int sel = mz >> 3;
    const float* X = (sel ? gx : zx) + (size_t)b * N_ * D_;
    const float* Y = (sel ? gy : zy) + (size_t)b * M_ * D_;
    float* C = out + (size_t)(1 + sel) * B_ * N_ * M_ + (size_t)b * N_ * M_;

    const int row0 = blockIdx.y * 128;
    const int col0 = blockIdx.x * 128;

    __shared__ float Xs[16][132];
    __shared__ float Ys[16][132];

    const int t  = threadIdx.x;
    const int lr = t >> 1;
    const int lk = (t & 1) * 8;
    const int ty = t >> 4;
    const int tx = t & 15;

    float acc[8][8];
#pragma unroll
    for (int r = 0; r < 8; ++r)
#pragma unroll
        for (int c = 0; c < 8; ++c) acc[r][c] = 0.f;

    for (int k0 = 0; k0 < D_; k0 += 16) {
        const float4 xv0 = *(const float4*)(X + (size_t)(row0 + lr) * D_ + k0 + lk);
        const float4 xv1 = *(const float4*)(X + (size_t)(row0 + lr) * D_ + k0 + lk + 4);
        const float4 yv0 = *(const float4*)(Y + (size_t)(col0 + lr) * D_ + k0 + lk);
        const float4 yv1 = *(const float4*)(Y + (size_t)(col0 + lr) * D_ + k0 + lk + 4);
        __syncthreads();
        Xs[lk + 0][lr] = xv0.x; Xs[lk + 1][lr] = xv0.y; Xs[lk + 2][lr] = xv0.z; Xs[lk + 3][lr] = xv0.w;
        Xs[lk + 4][lr] = xv1.x; Xs[lk + 5][lr] = xv1.y; Xs[lk + 6][lr] = xv1.z; Xs[lk + 7][lr] = xv1.w;
        Ys[lk + 0][lr] = yv0.x; Ys[lk + 1][lr] = yv0.y; Ys[lk + 2][lr] = yv0.z; Ys[lk + 3][lr] = yv0.w;
        Ys[lk + 4][lr] = yv1.x; Ys[lk + 5][lr] = yv1.y; Ys[lk + 6][lr] = yv1.z; Ys[lk + 7][lr] = yv1.w;
        __syncthreads();
#pragma unroll
        for (int kk = 0; kk < 16; ++kk) {
            float a0[8], b0[8];
            *(float4*)(a0)     = *(const float4*)&Xs[kk][ty * 8];
            *(float4*)(a0 + 4) = *(const float4*)&Xs[kk][ty * 8 + 4];
            *(float4*)(b0)     = *(const float4*)&Ys[kk][tx * 8];
            *(float4*)(b0 + 4) = *(const float4*)&Ys[kk][tx * 8 + 4];
#pragma unroll
            for (int r = 0; r < 8; ++r)
#pragma unroll
                for (int c = 0; c < 8; ++c)
                    acc[r][c] = fmaf(a0[r], b0[c], acc[r][c]);
        }
    }

#pragma unroll
    for (int r = 0; r < 8; ++r) {
        const int row = row0 + ty * 8 + r;
#pragma unroll
        for (int c4 = 0; c4 < 8; c4 += 4) {
            float4 v;
            float* vp = &v.x;
#pragma unroll
            for (int q = 0; q < 4; ++q) {
                const float x = acc[r][c4 + q];
                const float l = log1pf(__expf(-fabsf(x)));
                vp[q] = sel ? (fminf(x, 0.f) - l)     // log_sigmoid
                            : (fmaxf(x, 0.f) + l);    // softplus
            }
            *(float4*)(C + (size_t)row * M_ + col0 + tx * 8 + c4) = v;
        }
    }
}

// ---------------------------------------------------------------------------
// Diagonalize: theta,A (row-major) -> g_tha (diag-major float2, pre-scaled).
// ---------------------------------------------------------------------------
__global__ void __launch_bounds__(256) diag_kernel(const float* __restrict__ out)
{
    const float* theta = out + (size_t)B_ * N_ * M_;
    const float* Ag    = out + (size_t)2 * B_ * N_ * M_;
    const int b  = blockIdx.z;
    const int i0 = blockIdx.y * 32;
    const int j0 = blockIdx.x * 32;

    __shared__ float sth[32 * 32];
    __shared__ float sa [32 * 32];

    const int t    = threadIdx.x;
    const int warp = t >> 5;
    const int lane = t & 31;

#pragma unroll
    for (int it = 0; it < 4; ++it) {
        const int r = warp + it * 8;
        const int c = lane;
        const size_t g = ((size_t)b * N_ + (i0 + r)) * M_ + (j0 + c);
        sth[r * 32 + c] = theta[g] * INV_LN2;
        sa [r * 32 + c] = Ag[g]    * INV_LN2;
    }
    __syncthreads();

    float2* dst = g_tha + (size_t)b * ND_ * N_;
#pragma unroll
    for (int dd0 = 0; dd0 < 64; dd0 += 8) {
        const int dd = dd0 + warp;
        const int il = lane;
        const int jl = dd - il;
        if ((unsigned)jl < 32u) {
            const int d = i0 + j0 + dd;
            dst[(size_t)d * N_ + (i0 + il)] = make_float2(sth[il * 32 + jl], sa[il * 32 + jl]);
        }
    }
}

// ---------------------------------------------------------------------------
// Undiagonalize: g_e (diag-major) -> aln (row-major).
// ---------------------------------------------------------------------------
__global__ void __launch_bounds__(256) undiag_kernel(float* __restrict__ out)
{
    const int b  = blockIdx.z;
    const int i0 = blockIdx.y * 32;
    const int j0 = blockIdx.x * 32;

    __shared__ float se[32 * 32];

    const int t    = threadIdx.x;
    const int warp = t >> 5;
    const int lane = t & 31;

    const float* src = g_e + (size_t)b * ND_ * N_;
#pragma unroll
    for (int dd0 = 0; dd0 < 64; dd0 += 8) {
        const int dd = dd0 + warp;
        const int il = lane;
        const int jl = dd - il;
        if ((unsigned)jl < 32u) {
            const int d = i0 + j0 + dd;
            se[il * 32 + jl] = src[(size_t)d * N_ + (i0 + il)];
        }
    }
    __syncthreads();

    float* alnB = out + (size_t)b * N_ * M_;
#pragma unroll
    for (int it = 0; it < 4; ++it) {
        const int r = warp + it * 8;
        const int c = lane;
        alnB[(size_t)(i0 + r) * M_ + (j0 + c)] = se[r * 32 + c];
    }
}

// ---------------------------------------------------------------------------
// Forward soft-NW: wavefront of 32x32 tiles. Warp w owns rows [32w, 32w+32);
// within a tile, 32 diagonal steps run in registers with shfl_up for the
// neighbor row. Warp-boundary row values go through a plain smem ring; the
// tile schedule (wave t: warp w runs chunk c = t - 2w) guarantees every ring
// read is >= 1 __syncthreads after its write. 47 barriers total.
// ---------------------------------------------------------------------------
__global__ void __launch_bounds__(512) nw_fwd_kernel()
{
    const int b    = blockIdx.x;
    const int tid  = threadIdx.x;
    const int wid  = tid >> 5;
    const int lane = tid & 31;
    const int r    = tid;          // row index, i = r + 1
    const int w0   = wid * 32;

    __shared__ float bndV[16][128];   // [wid][d & 127] — lane31 V of warp wid
    for (int i = tid; i < 16 * 128; i += 512) ((float*)bndV)[i] = NEGL;
    __syncthreads();

    const float2* THA = g_tha + (size_t)b * ND_ * N_;
    float2*       Wb  = g_w   + (size_t)b * ND_ * N_;

    // 8-deep rolling register queue for (theta, A) along own row
    float2 th[8];
#pragma unroll
    for (int q = 0; q < 8; ++q) th[q] = THA[(size_t)(w0 + q) * N_ + r];

    float vp     = NEGL;                     // my V at previous diagonal
    float nbPrev = (tid == 0) ? 0.f : NEGL;  // neighbor V two diagonals back (V[0,0]=0 seed)

    for (int t = 0; t < 47; ++t) {
        const int c = t - 2 * wid;
        if (c >= 0 && c < 17) {
            const int d0 = w0 + 32 * c;
#pragma unroll
            for (int s = 0; s < 32; ++s) {
                const int d = d0 + s;
                const float2 ta = th[s & 7];
                {   // prefetch d+8 (clamped; out-of-band values are never used)
                    int dp = d + 8; if (dp > ND_ - 1) dp = ND_ - 1;
                    th[s & 7] = THA[(size_t)dp * N_ + r];
                }
                float nb = __shfl_up_sync(0xffffffffu, vp, 1);
                if (lane == 0) nb = (wid > 0) ? bndV[wid - 1][(d - 1) & 127] : NEGL;

                const float x0 = ta.y + nb;        // A + V[i-1, j]
                const float x2 = ta.y + vp;        // A + V[i,   j-1]
                const float dg = nbPrev;           //     V[i-1, j-1]
                const float m  = fmaxf(fmaxf(x0, x2), dg);
                const float e0 = ex2f_(x0 - m);
                const float e1 = ex2f_(dg - m);
                const float e2 = ex2f_(x2 - m);
                const float ss = e0 + e1 + e2;
                const float rr = rcpf_(ss);
                const float v  = ta.x + m + lg2f_(ss);

                const bool active = (unsigned)(d - r) < (unsigned)M_;
                if (active) {
                    Wb[(size_t)d * N_ + r] = make_float2(e0 * rr, e2 * rr);
                    vp = v;
                    if (lane == 31 && wid < 15) bndV[wid][d & 127] = v;
                }
                nbPrev = nb;
            }
        }
        __syncthreads();
    }
}

// ---------------------------------------------------------------------------
// Backward soft-NW: mirrored tile wavefront (dependency flows high->low rows).
// E[i,j] = E[i+1,j]*wU(i+1,j) + E[i,j+1]*wL(i,j+1) + E[i+1,j+1]*wD(i+1,j+1),
// E[N,M] = 1, wD = 1 - wU - wL. Zero weights/E outside the valid region make
// all masking implicit. Wave t: warp w runs chunk cc = t - 2*(15 - w).
// ---------------------------------------------------------------------------
__global__ void __launch_bounds__(512) nw_bwd_kernel()
{
    const int b    = blockIdx.x;
    const int tid  = threadIdx.x;
    const int wid  = tid >> 5;
    const int lane = tid & 31;
    const int r    = tid;
    const int w0   = wid * 32;
    const int dTop = w0 + 542;

    __shared__ float  eRing[15][128];   // [wid][d & 127] — lane0 E of warp wid+1
    __shared__ float2 wRing[15][128];   // matching own-row W of that lane
    for (int i = tid; i < 15 * 128; i += 512) {
        ((float*)eRing)[i]  = 0.f;
        ((float2*)wRing)[i] = make_float2(0.f, 0.f);
    }
    __syncthreads();

    const float2* Wb = g_w + (size_t)b * ND_ * N_;
    float*        Eb = g_e + (size_t)b * ND_ * N_;

    // 8-deep rolling register queue for own-row weights W[d][r] (descending d)
    float2 wq8[8];
#pragma unroll
    for (int q = 0; q < 8; ++q) wq8[q] = Wb[(size_t)(dTop - q) * N_ + r];

    float2 wp      = make_float2(0.f, 0.f);  // W[d+1][r]
    float  ep      = 0.f;                    // my E at d+1
    float  nbEPrev = 0.f;                    // neighbor (row r+1) E at d+2
    float2 nbWPrev = make_float2(0.f, 0.f);  // neighbor W at d+2

    for (int t = 0; t < 47; ++t) {
        const int cc = t - 2 * (15 - wid);
        if (cc >= 0 && cc < 17) {
#pragma unroll
            for (int s = 0; s < 32; ++s) {
                const int d = dTop - 32 * cc - s;
                const float2 wq = wq8[s & 7];     // W[d][r]
                {   // prefetch d-8 (clamped; out-of-band values never used)
                    int dp = d - 8; if (dp < 0) dp = 0;
                    wq8[s & 7] = Wb[(size_t)dp * N_ + r];
                }
                float nbE  = __shfl_down_sync(0xffffffffu, ep, 1);
                float nbWx = __shfl_down_sync(0xffffffffu, wp.x, 1);
                float nbWy = __shfl_down_sync(0xffffffffu, wp.y, 1);
                if (lane == 31) {
                    if (wid < 15) {
                        nbE = eRing[wid][(d + 1) & 127];
                        const float2 wv = wRing[wid][(d + 1) & 127];
                        nbWx = wv.x; nbWy = wv.y;
                    } else {
                        nbE = 0.f; nbWx = 0.f; nbWy = 0.f;
                    }
                }

                float e = nbE * nbWx                                  // E[i+1,j]   * wU(i+1,j)
                        + ep  * wp.y                                  // E[i,j+1]   * wL(i,j+1)
                        + nbEPrev * (1.f - nbWPrev.x - nbWPrev.y);    // E[i+1,j+1] * wD(i+1,j+1)
                if (r == 511 && d == 1022) e = 1.f;                   // base case E[N,M]

                const bool active = (unsigned)(d - r) < (unsigned)M_;
                if (active) {
                    Eb[(size_t)d * N_ + r] = e;
                    ep = e;
                    if (lane == 0 && wid > 0) {
                        wRing[wid - 1][d & 127] = wq;
                        eRing[wid - 1][d & 127] = e;
                    }
                }
                nbEPrev = nbE;
                nbWPrev = make_float2(nbWx, nbWy);
                wp = wq;
            }
        }
        __syncthreads();
    }
}

// ---------------------------------------------------------------------------
// launch
// ---------------------------------------------------------------------------
extern "C" void kernel_launch(void* const* d_in, const int* in_sizes, int n_in,
                              void* d_out, int out_size)
{
    const float* zx = (const float*)d_in[0];
    const float* zy = (const float*)d_in[1];
    const float* gx = (const float*)d_in[2];
    const float* gy = (const float*)d_in[3];
    float* out = (float*)d_out;   // [aln | theta | A]

    dim3 ggrid(M_ / 128, N_ / 128, 2 * B_);
    gemm_act_kernel<<<ggrid, 256>>>(zx, zy, gx, gy, out);

    dim3 tgrid(M_ / 32, N_ / 32, B_);
    diag_kernel<<<tgrid, 256>>>(out);
    nw_fwd_kernel<<<B_, 512>>>();
    nw_bwd_kernel<<<B_, 512>>>();
    undiag_kernel<<<tgrid, 256>>>(out);
}

// round 7
// speedup vs baseline: 3.0170x; 1.3235x over previous
#include <cuda_runtime.h>
#include <math.h>

constexpr int B_  = 8;
constexpr int N_  = 512;
constexpr int M_  = 512;
constexpr int D_  = 512;
constexpr int ND_ = N_ + M_ - 1;   // 1023 anti-diagonals
constexpr float NEGL    = -1.0e9f;
constexpr float INV_LN2 = 1.44269504088896340736f;

// Diagonal-major scratch (zero-initialized; invalid slots are never written,
// so they stay zero — bwd relies on this for implicit masking).
__device__ float2 g_tha[(size_t)B_ * ND_ * N_];
__device__ float2 g_w  [(size_t)B_ * ND_ * N_];
__device__ float  g_e  [(size_t)B_ * ND_ * N_];

__device__ __forceinline__ float ex2f_(float x) { float y; asm("ex2.approx.ftz.f32 %0, %1;" : "=f"(y) : "f"(x)); return y; }
__device__ __forceinline__ float lg2f_(float x) { float y; asm("lg2.approx.f32 %0, %1;"     : "=f"(y) : "f"(x)); return y; }
__device__ __forceinline__ float rcpf_(float x) { float y; asm("rcp.approx.f32 %0, %1;"     : "=f"(y) : "f"(x)); return y; }

// ---------------------------------------------------------------------------
// GEMM + activation (unchanged): 128x128 tile, 256 thr, 8x8 micro.
// ---------------------------------------------------------------------------
__global__ void __launch_bounds__(256, 2) gemm_act_kernel(
    const float* __restrict__ zx, const float* __restrict__ zy,
    const float* __restrict__ gx, const float* __restrict__ gy,
    float* __restrict__ out)
{
    const int mz  = blockIdx.z;
    const int b   = mz & 7;
    const int sel = mz >> 3;
    const float* X = (sel ? gx : zx) + (size_t)b * N_ * D_;
    const float* Y = (sel ? gy : zy) + (size_t)b * M_ * D_;
    float* C = out + (size_t)(1 + sel) * B_ * N_ * M_ + (size_t)b * N_ * M_;

    const int row0 = blockIdx.y * 128;
    const int col0 = blockIdx.x * 128;

    __shared__ float Xs[16][132];
    __shared__ float Ys[16][132];

    const int t  = threadIdx.x;
    const int lr = t >> 1;
    const int lk = (t & 1) * 8;
    const int ty = t >> 4;
    const int tx = t & 15;

    float acc[8][8];
#pragma unroll
    for (int r = 0; r < 8; ++r)
#pragma unroll
        for (int c = 0; c < 8; ++c) acc[r][c] = 0.f;

    for (int k0 = 0; k0 < D_; k0 += 16) {
        const float4 xv0 = *(const float4*)(X + (size_t)(row0 + lr) * D_ + k0 + lk);
        const float4 xv1 = *(const float4*)(X + (size_t)(row0 + lr) * D_ + k0 + lk + 4);
        const float4 yv0 = *(const float4*)(Y + (size_t)(col0 + lr) * D_ + k0 + lk);
        const float4 yv1 = *(const float4*)(Y + (size_t)(col0 + lr) * D_ + k0 + lk + 4);
        __syncthreads();
        Xs[lk + 0][lr] = xv0.x; Xs[lk + 1][lr] = xv0.y; Xs[lk + 2][lr] = xv0.z; Xs[lk + 3][lr] = xv0.w;
        Xs[lk + 4][lr] = xv1.x; Xs[lk + 5][lr] = xv1.y; Xs[lk + 6][lr] = xv1.z; Xs[lk + 7][lr] = xv1.w;
        Ys[lk + 0][lr] = yv0.x; Ys[lk + 1][lr] = yv0.y; Ys[lk + 2][lr] = yv0.z; Ys[lk + 3][lr] = yv0.w;
        Ys[lk + 4][lr] = yv1.x; Ys[lk + 5][lr] = yv1.y; Ys[lk + 6][lr] = yv1.z; Ys[lk + 7][lr] = yv1.w;
        __syncthreads();
#pragma unroll
        for (int kk = 0; kk < 16; ++kk) {
            float a0[8], b0[8];
            *(float4*)(a0)     = *(const float4*)&Xs[kk][ty * 8];
            *(float4*)(a0 + 4) = *(const float4*)&Xs[kk][ty * 8 + 4];
            *(float4*)(b0)     = *(const float4*)&Ys[kk][tx * 8];
            *(float4*)(b0 + 4) = *(const float4*)&Ys[kk][tx * 8 + 4];
#pragma unroll
            for (int r = 0; r < 8; ++r)
#pragma unroll
                for (int c = 0; c < 8; ++c)
                    acc[r][c] = fmaf(a0[r], b0[c], acc[r][c]);
        }
    }

#pragma unroll
    for (int r = 0; r < 8; ++r) {
        const int row = row0 + ty * 8 + r;
#pragma unroll
        for (int c4 = 0; c4 < 8; c4 += 4) {
            float4 v;
            float* vp = &v.x;
#pragma unroll
            for (int q = 0; q < 4; ++q) {
                const float x = acc[r][c4 + q];
                const float l = log1pf(__expf(-fabsf(x)));
                vp[q] = sel ? (fminf(x, 0.f) - l)     // log_sigmoid
                            : (fmaxf(x, 0.f) + l);    // softplus
            }
            *(float4*)(C + (size_t)row * M_ + col0 + tx * 8 + c4) = v;
        }
    }
}

// ---------------------------------------------------------------------------
// Diagonalize: theta,A (row-major) -> g_tha (diag-major float2, pre-scaled).
// ---------------------------------------------------------------------------
__global__ void __launch_bounds__(256) diag_kernel(const float* __restrict__ out)
{
    const float* theta = out + (size_t)B_ * N_ * M_;
    const float* Ag    = out + (size_t)2 * B_ * N_ * M_;
    const int b  = blockIdx.z;
    const int i0 = blockIdx.y * 32;
    const int j0 = blockIdx.x * 32;

    __shared__ float sth[32 * 32];
    __shared__ float sa [32 * 32];

    const int t    = threadIdx.x;
    const int warp = t >> 5;
    const int lane = t & 31;

#pragma unroll
    for (int it = 0; it < 4; ++it) {
        const int r = warp + it * 8;
        const int c = lane;
        const size_t g = ((size_t)b * N_ + (i0 + r)) * M_ + (j0 + c);
        sth[r * 32 + c] = theta[g] * INV_LN2;
        sa [r * 32 + c] = Ag[g]    * INV_LN2;
    }
    __syncthreads();

    float2* dst = g_tha + (size_t)b * ND_ * N_;
#pragma unroll
    for (int dd0 = 0; dd0 < 64; dd0 += 8) {
        const int dd = dd0 + warp;
        const int il = lane;
        const int jl = dd - il;
        if ((unsigned)jl < 32u) {
            const int d = i0 + j0 + dd;
            dst[(size_t)d * N_ + (i0 + il)] = make_float2(sth[il * 32 + jl], sa[il * 32 + jl]);
        }
    }
}

// ---------------------------------------------------------------------------
// Undiagonalize: g_e (diag-major) -> aln (row-major).
// ---------------------------------------------------------------------------
__global__ void __launch_bounds__(256) undiag_kernel(float* __restrict__ out)
{
    const int b  = blockIdx.z;
    const int i0 = blockIdx.y * 32;
    const int j0 = blockIdx.x * 32;

    __shared__ float se[32 * 32];

    const int t    = threadIdx.x;
    const int warp = t >> 5;
    const int lane = t & 31;

    const float* src = g_e + (size_t)b * ND_ * N_;
#pragma unroll
    for (int dd0 = 0; dd0 < 64; dd0 += 8) {
        const int dd = dd0 + warp;
        const int il = lane;
        const int jl = dd - il;
        if ((unsigned)jl < 32u) {
            const int d = i0 + j0 + dd;
            se[il * 32 + jl] = src[(size_t)d * N_ + (i0 + il)];
        }
    }
    __syncthreads();

    float* alnB = out + (size_t)b * N_ * M_;
#pragma unroll
    for (int it = 0; it < 4; ++it) {
        const int r = warp + it * 8;
        const int c = lane;
        alnB[(size_t)(i0 + r) * M_ + (j0 + c)] = se[r * 32 + c];
    }
}

// ---------------------------------------------------------------------------
// Forward soft-NW: tile wavefront, branchless step body. Ring reads are
// unconditional broadcast LDS + SEL; all stores are single predicated
// instructions (no BSSY/BSYNC in the hot loop).
// ---------------------------------------------------------------------------
__global__ void __launch_bounds__(512) nw_fwd_kernel()
{
    const int b    = blockIdx.x;
    const int tid  = threadIdx.x;
    const int wid  = tid >> 5;
    const int lane = tid & 31;
    const int r    = tid;
    const int w0   = wid * 32;

    __shared__ float bndV[17][128];   // row 16 never written: NEGL boundary
    for (int i = tid; i < 17 * 128; i += 512) ((float*)bndV)[i] = NEGL;
    __syncthreads();

    const float2* THA = g_tha + (size_t)b * ND_ * N_;
    float2*       Wb  = g_w   + (size_t)b * ND_ * N_;

    float*       ringWr = bndV[wid];
    const float* ringRd = bndV[wid == 0 ? 16 : wid - 1];

    float2 th[8];
#pragma unroll
    for (int q = 0; q < 8; ++q) th[q] = THA[(size_t)(w0 + q) * N_ + r];

    float vp     = NEGL;
    float nbPrev = (tid == 0) ? 0.f : NEGL;   // seeds V[0,0] = 0 for cell (0,0)

    for (int t = 0; t < 47; ++t) {
        const int c = t - 2 * wid;
        if (c >= 0 && c < 17) {
            const int d0 = w0 + 32 * c;
#pragma unroll
            for (int s = 0; s < 32; ++s) {
                const int d = d0 + s;
                const float2 ta = th[s & 7];
                int dp = d + 8; dp = dp > ND_ - 1 ? ND_ - 1 : dp;
                th[s & 7] = THA[(size_t)dp * N_ + r];

                const float ringv = ringRd[(d - 1) & 127];     // broadcast LDS
                float nb = __shfl_up_sync(0xffffffffu, vp, 1);
                nb = (lane == 0) ? ringv : nb;

                const float x0 = ta.y + nb;        // A + V[i-1, j]
                const float x2 = ta.y + vp;        // A + V[i,   j-1]
                const float dg = nbPrev;           //     V[i-1, j-1]
                const float m  = fmaxf(fmaxf(x0, x2), dg);
                const float e0 = ex2f_(x0 - m);
                const float e1 = ex2f_(dg - m);
                const float e2 = ex2f_(x2 - m);
                const float ss = e0 + e1 + e2;
                const float rr = rcpf_(ss);
                const float v  = ta.x + m + lg2f_(ss);

                const bool active = (unsigned)(d - r) < (unsigned)M_;
                if (active) Wb[(size_t)d * N_ + r] = make_float2(e0 * rr, e2 * rr);
                vp = active ? v : vp;
                nbPrev = nb;
                if (lane == 31) ringWr[d & 127] = vp;          // @p STS.32
            }
        }
        __syncthreads();
    }
}

// ---------------------------------------------------------------------------
// Backward soft-NW: mirrored tile wavefront, branchless step body.
// E[i,j] = E[i+1,j]*wU(i+1,j) + E[i,j+1]*wL(i,j+1) + E[i+1,j+1]*wD(i+1,j+1),
// E[N,M]=1, wD = 1-wU-wL. Ring packed as float4 {E, wU, wL, -}: one LDS.128
// broadcast per step, one @p STS.128 per step.
// ---------------------------------------------------------------------------
__global__ void __launch_bounds__(512) nw_bwd_kernel()
{
    const int b    = blockIdx.x;
    const int tid  = threadIdx.x;
    const int wid  = tid >> 5;
    const int lane = tid & 31;
    const int r    = tid;
    const int w0   = wid * 32;
    const int dTop = w0 + 542;

    __shared__ float4 ringB[17][128];   // row 16 never written: zero boundary
    for (int i = tid; i < 17 * 128; i += 512)
        ((float4*)ringB)[i] = make_float4(0.f, 0.f, 0.f, 0.f);
    __syncthreads();

    const float2* Wb = g_w + (size_t)b * ND_ * N_;
    float*        Eb = g_e + (size_t)b * ND_ * N_;

    float4*       ringWr = ringB[wid];
    const float4* ringRd = ringB[wid + 1];   // warp 15 -> row 16 (zeros)

    float2 wq8[8];
#pragma unroll
    for (int q = 0; q < 8; ++q) wq8[q] = Wb[(size_t)(dTop - q) * N_ + r];

    float2 wp      = make_float2(0.f, 0.f);  // W[d+1][r]
    float  ep      = 0.f;                    // my E at d+1
    float  nbEPrev = 0.f;                    // neighbor E at d+2
    float  nbWxP   = 0.f, nbWyP = 0.f;       // neighbor W at d+2

    for (int t = 0; t < 47; ++t) {
        const int cc = t - 2 * (15 - wid);
        if (cc >= 0 && cc < 17) {
            const int d0 = dTop - 32 * cc;
#pragma unroll
            for (int s = 0; s < 32; ++s) {
                const int d = d0 - s;
                const float2 wq = wq8[s & 7];            // W[d][r]
                int dp = d - 8; dp = dp < 0 ? 0 : dp;
                wq8[s & 7] = Wb[(size_t)dp * N_ + r];

                const float4 rv = ringRd[(d + 1) & 127]; // broadcast LDS.128
                float nbE  = __shfl_down_sync(0xffffffffu, ep,   1);
                float nbWx = __shfl_down_sync(0xffffffffu, wp.x, 1);
                float nbWy = __shfl_down_sync(0xffffffffu, wp.y, 1);
                nbE  = (lane == 31) ? rv.x : nbE;
                nbWx = (lane == 31) ? rv.y : nbWx;
                nbWy = (lane == 31) ? rv.z : nbWy;

                float e = nbE * nbWx                         // E[i+1,j]   * wU(i+1,j)
                        + ep  * wp.y                         // E[i,j+1]   * wL(i,j+1)
                        + nbEPrev * (1.f - nbWxP - nbWyP);   // E[i+1,j+1] * wD(i+1,j+1)
                e = (d == 1022 && r == 511) ? 1.f : e;       // base case E[N,M]

                const bool active = (unsigned)(d - r) < (unsigned)M_;
                if (active) Eb[(size_t)d * N_ + r] = e;      // @p STG.32
                ep = active ? e : ep;
                nbEPrev = nbE; nbWxP = nbWx; nbWyP = nbWy;
                wp = wq;
                if (lane == 0) ringWr[d & 127] = make_float4(ep, wq.x, wq.y, 0.f); // @p STS.128
            }
        }
        __syncthreads();
    }
}

// ---------------------------------------------------------------------------
// launch
// ---------------------------------------------------------------------------
extern "C" void kernel_launch(void* const* d_in, const int* in_sizes, int n_in,
                              void* d_out, int out_size)
{
    const float* zx = (const float*)d_in[0];
    const float* zy = (const float*)d_in[1];
    const float* gx = (const float*)d_in[2];
    const float* gy = (const float*)d_in[3];
    float* out = (float*)d_out;   // [aln | theta | A]

    dim3 ggrid(M_ / 128, N_ / 128, 2 * B_);
    gemm_act_kernel<<<ggrid, 256>>>(zx, zy, gx, gy, out);

    dim3 tgrid(M_ / 32, N_ / 32, B_);
    diag_kernel<<<tgrid, 256>>>(out);
    nw_fwd_kernel<<<B_, 512>>>();
    nw_bwd_kernel<<<B_, 512>>>();
    undiag_kernel<<<tgrid, 256>>>(out);
}

// round 8
// speedup vs baseline: 3.3730x; 1.1180x over previous
#include <cuda_runtime.h>
#include <math.h>

constexpr int B_  = 8;
constexpr int N_  = 512;
constexpr int M_  = 512;
constexpr int D_  = 512;
constexpr int ND_ = N_ + M_ - 1;   // 1023 anti-diagonals
constexpr float NEGL    = -1.0e9f;
constexpr float INV_LN2 = 1.44269504088896340736f;

// Diagonal-major scratch (zero-initialized; invalid slots are never written,
// so they stay zero — bwd relies on this for implicit masking).
__device__ float2 g_tha[(size_t)B_ * ND_ * N_];
__device__ float2 g_w  [(size_t)B_ * ND_ * N_];
__device__ float  g_e  [(size_t)B_ * ND_ * N_];

__device__ __forceinline__ float ex2f_(float x) { float y; asm("ex2.approx.ftz.f32 %0, %1;" : "=f"(y) : "f"(x)); return y; }
__device__ __forceinline__ float lg2f_(float x) { float y; asm("lg2.approx.f32 %0, %1;"     : "=f"(y) : "f"(x)); return y; }
__device__ __forceinline__ float rcpf_(float x) { float y; asm("rcp.approx.f32 %0, %1;"     : "=f"(y) : "f"(x)); return y; }

// ---------------------------------------------------------------------------
// GEMM + activation (unchanged): 128x128 tile, 256 thr, 8x8 micro.
// ---------------------------------------------------------------------------
__global__ void __launch_bounds__(256, 2) gemm_act_kernel(
    const float* __restrict__ zx, const float* __restrict__ zy,
    const float* __restrict__ gx, const float* __restrict__ gy,
    float* __restrict__ out)
{
    const int mz  = blockIdx.z;
    const int b   = mz & 7;
    const int sel = mz >> 3;
    const float* X = (sel ? gx : zx) + (size_t)b * N_ * D_;
    const float* Y = (sel ? gy : zy) + (size_t)b * M_ * D_;
    float* C = out + (size_t)(1 + sel) * B_ * N_ * M_ + (size_t)b * N_ * M_;

    const int row0 = blockIdx.y * 128;
    const int col0 = blockIdx.x * 128;

    __shared__ float Xs[16][132];
    __shared__ float Ys[16][132];

    const int t  = threadIdx.x;
    const int lr = t >> 1;
    const int lk = (t & 1) * 8;
    const int ty = t >> 4;
    const int tx = t & 15;

    float acc[8][8];
#pragma unroll
    for (int r = 0; r < 8; ++r)
#pragma unroll
        for (int c = 0; c < 8; ++c) acc[r][c] = 0.f;

    for (int k0 = 0; k0 < D_; k0 += 16) {
        const float4 xv0 = *(const float4*)(X + (size_t)(row0 + lr) * D_ + k0 + lk);
        const float4 xv1 = *(const float4*)(X + (size_t)(row0 + lr) * D_ + k0 + lk + 4);
        const float4 yv0 = *(const float4*)(Y + (size_t)(col0 + lr) * D_ + k0 + lk);
        const float4 yv1 = *(const float4*)(Y + (size_t)(col0 + lr) * D_ + k0 + lk + 4);
        __syncthreads();
        Xs[lk + 0][lr] = xv0.x; Xs[lk + 1][lr] = xv0.y; Xs[lk + 2][lr] = xv0.z; Xs[lk + 3][lr] = xv0.w;
        Xs[lk + 4][lr] = xv1.x; Xs[lk + 5][lr] = xv1.y; Xs[lk + 6][lr] = xv1.z; Xs[lk + 7][lr] = xv1.w;
        Ys[lk + 0][lr] = yv0.x; Ys[lk + 1][lr] = yv0.y; Ys[lk + 2][lr] = yv0.z; Ys[lk + 3][lr] = yv0.w;
        Ys[lk + 4][lr] = yv1.x; Ys[lk + 5][lr] = yv1.y; Ys[lk + 6][lr] = yv1.z; Ys[lk + 7][lr] = yv1.w;
        __syncthreads();
#pragma unroll
        for (int kk = 0; kk < 16; ++kk) {
            float a0[8], b0[8];
            *(float4*)(a0)     = *(const float4*)&Xs[kk][ty * 8];
            *(float4*)(a0 + 4) = *(const float4*)&Xs[kk][ty * 8 + 4];
            *(float4*)(b0)     = *(const float4*)&Ys[kk][tx * 8];
            *(float4*)(b0 + 4) = *(const float4*)&Ys[kk][tx * 8 + 4];
#pragma unroll
            for (int r = 0; r < 8; ++r)
#pragma unroll
                for (int c = 0; c < 8; ++c)
                    acc[r][c] = fmaf(a0[r], b0[c], acc[r][c]);
        }
    }

#pragma unroll
    for (int r = 0; r < 8; ++r) {
        const int row = row0 + ty * 8 + r;
#pragma unroll
        for (int c4 = 0; c4 < 8; c4 += 4) {
            float4 v;
            float* vp = &v.x;
#pragma unroll
            for (int q = 0; q < 4; ++q) {
                const float x = acc[r][c4 + q];
                const float l = log1pf(__expf(-fabsf(x)));
                vp[q] = sel ? (fminf(x, 0.f) - l)     // log_sigmoid
                            : (fmaxf(x, 0.f) + l);    // softplus
            }
            *(float4*)(C + (size_t)row * M_ + col0 + tx * 8 + c4) = v;
        }
    }
}

// ---------------------------------------------------------------------------
// Diagonalize: theta,A (row-major) -> g_tha (diag-major float2, pre-scaled).
// ---------------------------------------------------------------------------
__global__ void __launch_bounds__(256) diag_kernel(const float* __restrict__ out)
{
    const float* theta = out + (size_t)B_ * N_ * M_;
    const float* Ag    = out + (size_t)2 * B_ * N_ * M_;
    const int b  = blockIdx.z;
    const int i0 = blockIdx.y * 32;
    const int j0 = blockIdx.x * 32;

    __shared__ float sth[32 * 32];
    __shared__ float sa [32 * 32];

    const int t    = threadIdx.x;
    const int warp = t >> 5;
    const int lane = t & 31;

#pragma unroll
    for (int it = 0; it < 4; ++it) {
        const int r = warp + it * 8;
        const int c = lane;
        const size_t g = ((size_t)b * N_ + (i0 + r)) * M_ + (j0 + c);
        sth[r * 32 + c] = theta[g] * INV_LN2;
        sa [r * 32 + c] = Ag[g]    * INV_LN2;
    }
    __syncthreads();

    float2* dst = g_tha + (size_t)b * ND_ * N_;
#pragma unroll
    for (int dd0 = 0; dd0 < 64; dd0 += 8) {
        const int dd = dd0 + warp;
        const int il = lane;
        const int jl = dd - il;
        if ((unsigned)jl < 32u) {
            const int d = i0 + j0 + dd;
            dst[(size_t)d * N_ + (i0 + il)] = make_float2(sth[il * 32 + jl], sa[il * 32 + jl]);
        }
    }
}

// ---------------------------------------------------------------------------
// Undiagonalize: g_e (diag-major) -> aln (row-major).
// ---------------------------------------------------------------------------
__global__ void __launch_bounds__(256) undiag_kernel(float* __restrict__ out)
{
    const int b  = blockIdx.z;
    const int i0 = blockIdx.y * 32;
    const int j0 = blockIdx.x * 32;

    __shared__ float se[32 * 32];

    const int t    = threadIdx.x;
    const int warp = t >> 5;
    const int lane = t & 31;

    const float* src = g_e + (size_t)b * ND_ * N_;
#pragma unroll
    for (int dd0 = 0; dd0 < 64; dd0 += 8) {
        const int dd = dd0 + warp;
        const int il = lane;
        const int jl = dd - il;
        if ((unsigned)jl < 32u) {
            const int d = i0 + j0 + dd;
            se[il * 32 + jl] = src[(size_t)d * N_ + (i0 + il)];
        }
    }
    __syncthreads();

    float* alnB = out + (size_t)b * N_ * M_;
#pragma unroll
    for (int it = 0; it < 4; ++it) {
        const int r = warp + it * 8;
        const int c = lane;
        alnB[(size_t)(i0 + r) * M_ + (j0 + c)] = se[r * 32 + c];
    }
}

// ---------------------------------------------------------------------------
// Forward soft-NW: tile wavefront, branchless step body, depth-16 prefetch.
// ---------------------------------------------------------------------------
__global__ void __launch_bounds__(512) nw_fwd_kernel()
{
    const int b    = blockIdx.x;
    const int tid  = threadIdx.x;
    const int wid  = tid >> 5;
    const int lane = tid & 31;
    const int r    = tid;
    const int w0   = wid * 32;

    __shared__ float bndV[17][128];   // row 16 never written: NEGL boundary
    for (int i = tid; i < 17 * 128; i += 512) ((float*)bndV)[i] = NEGL;
    __syncthreads();

    const float2* THA = g_tha + (size_t)b * ND_ * N_;
    float2*       Wb  = g_w   + (size_t)b * ND_ * N_;

    float*       ringWr = bndV[wid];
    const float* ringRd = bndV[wid == 0 ? 16 : wid - 1];

    float2 th[16];
#pragma unroll
    for (int q = 0; q < 16; ++q) th[q] = THA[(size_t)(w0 + q) * N_ + r];

    float vp     = NEGL;
    float nbPrev = (tid == 0) ? 0.f : NEGL;   // seeds V[0,0] = 0 for cell (0,0)

    for (int t = 0; t < 47; ++t) {
        const int c = t - 2 * wid;
        if (c >= 0 && c < 17) {
            const int d0 = w0 + 32 * c;
#pragma unroll
            for (int s = 0; s < 32; ++s) {
                const int d = d0 + s;
                const float2 ta = th[s & 15];
                int dp = d + 16; dp = dp > ND_ - 1 ? ND_ - 1 : dp;
                th[s & 15] = THA[(size_t)dp * N_ + r];

                const float ringv = ringRd[(d - 1) & 127];     // broadcast LDS
                float nb = __shfl_up_sync(0xffffffffu, vp, 1);
                nb = (lane == 0) ? ringv : nb;

                const float x0 = ta.y + nb;        // A + V[i-1, j]
                const float x2 = ta.y + vp;        // A + V[i,   j-1]
                const float dg = nbPrev;           //     V[i-1, j-1]
                const float m  = fmaxf(fmaxf(x0, x2), dg);
                const float e0 = ex2f_(x0 - m);
                const float e1 = ex2f_(dg - m);
                const float e2 = ex2f_(x2 - m);
                const float ss = e0 + e1 + e2;
                const float rr = rcpf_(ss);
                const float v  = ta.x + m + lg2f_(ss);

                const bool active = (unsigned)(d - r) < (unsigned)M_;
                if (active) Wb[(size_t)d * N_ + r] = make_float2(e0 * rr, e2 * rr);
                vp = active ? v : vp;
                nbPrev = nb;
                if (lane == 31) ringWr[d & 127] = vp;          // @p STS.32
            }
        }
        __syncthreads();
    }
}

// ---------------------------------------------------------------------------
// Backward soft-NW: tile wavefront with OFF-CHAIN weights. Each thread
// prefetches two diag-major W streams (own row r, and row r+1) with
// depth-16 register queues; all three recurrence coefficients come from the
// queues, so the only serial chain is shfl(E) -> 2 FMA -> SEL. The smem ring
// carries just the boundary E value (float).
//   E[i,j] = E[i+1,j]*wU(i+1,j) + E[i,j+1]*wL(i,j+1) + E[i+1,j+1]*wD(i+1,j+1)
//   wU = W[d+1][r+1].x, wL = W[d+1][r].y, wD = 1 - sum(W[d+2][r+1])
// ---------------------------------------------------------------------------
__global__ void __launch_bounds__(512) nw_bwd_kernel()
{
    const int b    = blockIdx.x;
    const int tid  = threadIdx.x;
    const int wid  = tid >> 5;
    const int lane = tid & 31;
    const int r    = tid;
    const int w0   = wid * 32;
    const int dTop = w0 + 542;
    const bool hasNext = (r + 1 < N_);   // row r+1 exists

    __shared__ float eRing[17][128];     // row 16 never written: zero boundary
    for (int i = tid; i < 17 * 128; i += 512) ((float*)eRing)[i] = 0.f;
    __syncthreads();

    const float2* Wb = g_w + (size_t)b * ND_ * N_;
    float*        Eb = g_e + (size_t)b * ND_ * N_;

    float*       ringWr = eRing[wid];
    const float* ringRd = eRing[wid + 1];   // warp 15 -> row 16 (zeros)

    const float2 zero2 = make_float2(0.f, 0.f);

    // depth-16 queues: slot g (global step, descending d) holds entries for
    // diagonal dd = dTop + 1 - g. qA = W[dd][r], qB = W[dd][r+1].
    float2 qA[16], qB[16];
#pragma unroll
    for (int q = 0; q < 16; ++q) {
        const int dd = dTop + 1 - q;
        const bool ok = (dd <= ND_ - 1);           // dd >= 0 always here
        qA[q] = ok ? Wb[(size_t)dd * N_ + r] : zero2;
        qB[q] = (ok && hasNext) ? Wb[(size_t)dd * N_ + r + 1] : zero2;
    }

    // bPrev = W[dTop+2][r+1] (coefficient for the first step's diagonal child)
    float2 bPrev = zero2;
    {
        const int dd = dTop + 2;
        if (dd <= ND_ - 1 && hasNext) bPrev = Wb[(size_t)dd * N_ + r + 1];
    }

    float ep      = 0.f;   // my E at d+1
    float nbEPrev = 0.f;   // neighbor E at d+2

    for (int t = 0; t < 47; ++t) {
        const int cc = t - 2 * (15 - wid);
        if (cc >= 0 && cc < 17) {
            const int d0 = dTop - 32 * cc;
#pragma unroll
            for (int s = 0; s < 32; ++s) {
                const int d = d0 - s;
                const float2 cA = qA[s & 15];    // W[d+1][r]
                const float2 cB = qB[s & 15];    // W[d+1][r+1]
                int dd = d - 15; dd = dd < 0 ? 0 : dd;      // refill for step d-16
                qA[s & 15] = Wb[(size_t)dd * N_ + r];
                qB[s & 15] = hasNext ? Wb[(size_t)dd * N_ + r + 1] : zero2;

                const float rv = ringRd[(d + 1) & 127];     // broadcast LDS
                float nbE = __shfl_down_sync(0xffffffffu, ep, 1);
                nbE = (lane == 31) ? rv : nbE;

                float e = nbE * cB.x                          // E[i+1,j]   * wU
                        + ep  * cA.y                          // E[i,j+1]   * wL
                        + nbEPrev * (1.f - bPrev.x - bPrev.y);// E[i+1,j+1] * wD
                e = (d == 1022 && r == 511) ? 1.f : e;        // base case E[N,M]

                const bool active = (unsigned)(d - r) < (unsigned)M_;
                const float ev = active ? e : 0.f;
                Eb[(size_t)d * N_ + r] = ev;                  // unconditional STG
                ep = active ? e : ep;
                nbEPrev = nbE;
                bPrev = cB;
                if (lane == 0) ringWr[d & 127] = ep;          // @p STS.32
            }
        }
        __syncthreads();
    }
}

// ---------------------------------------------------------------------------
// launch
// ---------------------------------------------------------------------------
extern "C" void kernel_launch(void* const* d_in, const int* in_sizes, int n_in,
                              void* d_out, int out_size)
{
    const float* zx = (const float*)d_in[0];
    const float* zy = (const float*)d_in[1];
    const float* gx = (const float*)d_in[2];
    const float* gy = (const float*)d_in[3];
    float* out = (float*)d_out;   // [aln | theta | A]

    dim3 ggrid(M_ / 128, N_ / 128, 2 * B_);
    gemm_act_kernel<<<ggrid, 256>>>(zx, zy, gx, gy, out);

    dim3 tgrid(M_ / 32, N_ / 32, B_);
    diag_kernel<<<tgrid, 256>>>(out);
    nw_fwd_kernel<<<B_, 512>>>();
    nw_bwd_kernel<<<B_, 512>>>();
    undiag_kernel<<<tgrid, 256>>>(out);
}